// round 1
// baseline (speedup 1.0000x reference)
#include <cuda_runtime.h>
#include <cuda_bf16.h>

// SpikeEncoder: rates = sigmoid(x @ W^T + b); spikes = (u < rates)
// x: [256,512] f32, W: [2048,512] f32, b: [2048] f32, u: [256,100,2048] f32
// out: spikes [256*100*2048] f32, then rates [256*2048] f32

#define BATCH 256
#define INPUT_DIM 512
#define NUM_NEURONS 2048
#define TIME_STEPS 100

#define BM 64
#define BN 64
#define BK 32

// ---------------------------------------------------------------------------
// Kernel A: tiled fp32 GEMM (C = x @ W^T + b) -> sigmoid -> rates
// grid (32, 4), 256 threads. Each thread computes a 4x4 micro-tile.
// Per-K-tile local accumulation (tree-ish) to keep rounding error low:
// spikes are a hard threshold, so rate accuracy controls spike flips.
// ---------------------------------------------------------------------------
__global__ __launch_bounds__(256, 2)
void rates_kernel(const float* __restrict__ x,
                  const float* __restrict__ W,
                  const float* __restrict__ bias,
                  float* __restrict__ rates) {
    __shared__ float As[BK][BM];   // x tile, k-major
    __shared__ float Bs[BK][BN];   // W tile, k-major

    const int tid   = threadIdx.x;
    const int nBase = blockIdx.x * BN;
    const int mBase = blockIdx.y * BM;

    const int tx = tid & 15;       // 0..15 -> neuron micro-tile
    const int ty = tid >> 4;       // 0..15 -> batch micro-tile
    const int m0 = ty * 4;
    const int n0 = tx * 4;

    float acc[4][4];
#pragma unroll
    for (int i = 0; i < 4; i++)
#pragma unroll
        for (int j = 0; j < 4; j++) acc[i][j] = 0.0f;

    for (int k0 = 0; k0 < INPUT_DIM; k0 += BK) {
        // Cooperative load: 2048 floats per tile = 512 float4, 256 threads x 2
#pragma unroll
        for (int l = 0; l < 2; l++) {
            const int f  = tid + l * 256;       // 0..511
            const int r  = f >> 3;              // row within tile (0..63)
            const int k4 = (f & 7) << 2;        // k offset (0,4,...,28)

            float4 va = *(const float4*)&x[(mBase + r) * INPUT_DIM + k0 + k4];
            As[k4 + 0][r] = va.x;
            As[k4 + 1][r] = va.y;
            As[k4 + 2][r] = va.z;
            As[k4 + 3][r] = va.w;

            float4 vb = *(const float4*)&W[(nBase + r) * INPUT_DIM + k0 + k4];
            Bs[k4 + 0][r] = vb.x;
            Bs[k4 + 1][r] = vb.y;
            Bs[k4 + 2][r] = vb.z;
            Bs[k4 + 3][r] = vb.w;
        }
        __syncthreads();

        // Local (per K-tile) accumulators -> tree-style combine for accuracy
        float tacc[4][4];
#pragma unroll
        for (int i = 0; i < 4; i++)
#pragma unroll
            for (int j = 0; j < 4; j++) tacc[i][j] = 0.0f;

#pragma unroll
        for (int k = 0; k < BK; k++) {
            float4 a = *(const float4*)&As[k][m0];
            float4 bv = *(const float4*)&Bs[k][n0];
            const float ar[4] = {a.x, a.y, a.z, a.w};
            const float br[4] = {bv.x, bv.y, bv.z, bv.w};
#pragma unroll
            for (int i = 0; i < 4; i++)
#pragma unroll
                for (int j = 0; j < 4; j++)
                    tacc[i][j] = fmaf(ar[i], br[j], tacc[i][j]);
        }

#pragma unroll
        for (int i = 0; i < 4; i++)
#pragma unroll
            for (int j = 0; j < 4; j++) acc[i][j] += tacc[i][j];

        __syncthreads();
    }

    // Epilogue: bias + sigmoid, vectorized store
    const float4 bvec = *(const float4*)&bias[nBase + n0];
    const float bb[4] = {bvec.x, bvec.y, bvec.z, bvec.w};
#pragma unroll
    for (int i = 0; i < 4; i++) {
        float4 out;
        float v[4];
#pragma unroll
        for (int j = 0; j < 4; j++) {
            float z = acc[i][j] + bb[j];
            v[j] = 1.0f / (1.0f + expf(-z));
        }
        out.x = v[0]; out.y = v[1]; out.z = v[2]; out.w = v[3];
        *(float4*)&rates[(mBase + m0 + i) * NUM_NEURONS + nBase + n0] = out;
    }
}

// ---------------------------------------------------------------------------
// Kernel B: streaming spike compare, float4-vectorized.
// total float4 elems = 256*100*2048/4 = 13,107,200 (exact multiple of 256)
// ---------------------------------------------------------------------------
__global__ __launch_bounds__(256)
void spike_kernel(const float4* __restrict__ u,
                  const float* __restrict__ rates,
                  float4* __restrict__ spikes) {
    const int i = blockIdx.x * blockDim.x + threadIdx.x;
    const long long base = (long long)i << 2;
    const int n  = (int)(base & (NUM_NEURONS - 1));          // 4-aligned
    const int bt = (int)(base >> 11);                         // b*T + t
    const int bb = bt / TIME_STEPS;

    const float4 r  = *(const float4*)&rates[((long long)bb << 11) + n];
    const float4 uu = u[i];
    float4 s;
    s.x = (uu.x < r.x) ? 1.0f : 0.0f;
    s.y = (uu.y < r.y) ? 1.0f : 0.0f;
    s.z = (uu.z < r.z) ? 1.0f : 0.0f;
    s.w = (uu.w < r.w) ? 1.0f : 0.0f;
    spikes[i] = s;
}

extern "C" void kernel_launch(void* const* d_in, const int* in_sizes, int n_in,
                              void* d_out, int out_size) {
    const float* x = (const float*)d_in[0];
    const float* W = (const float*)d_in[1];
    const float* b = (const float*)d_in[2];
    const float* u = (const float*)d_in[3];

    float* out    = (float*)d_out;
    float* spikes = out;                                            // 52,428,800
    float* rates  = out + (long long)BATCH * TIME_STEPS * NUM_NEURONS; // +524,288

    dim3 gridA(NUM_NEURONS / BN, BATCH / BM);   // (32, 4)
    rates_kernel<<<gridA, 256>>>(x, W, b, rates);

    const int total4 = BATCH * TIME_STEPS * NUM_NEURONS / 4;        // 13,107,200
    spike_kernel<<<total4 / 256, 256>>>((const float4*)u, rates, (float4*)spikes);
}

// round 2
// speedup vs baseline: 1.0561x; 1.0561x over previous
#include <cuda_runtime.h>
#include <cuda_bf16.h>

// SpikeEncoder: rates = sigmoid(x @ W^T + b); spikes = (u < rates)
// x: [256,512] f32, W: [2048,512] f32, b: [2048] f32, u: [256,100,2048] f32
// out: spikes [256*100*2048] f32, then rates [256*2048] f32

#define BATCH 256
#define INPUT_DIM 512
#define NUM_NEURONS 2048
#define TIME_STEPS 100

#define BM 64
#define BN 64
#define BK 32
#define KTILES (INPUT_DIM / BK)   // 16

// ---------------------------------------------------------------------------
// Kernel A: tiled fp32 GEMM (C = x @ W^T + b) -> sigmoid -> rates
// Double-buffered smem + global->reg prefetch + register fragment
// double-buffering so the 16-FFMA/k-step stream hides LDS/GMEM latency.
// grid (32, 4), 256 threads, 4x4 micro-tile per thread.
// ---------------------------------------------------------------------------
__global__ __launch_bounds__(256)
void rates_kernel(const float* __restrict__ x,
                  const float* __restrict__ W,
                  const float* __restrict__ bias,
                  float* __restrict__ rates) {
    __shared__ float As[2][BK][BM];   // x tile, k-major
    __shared__ float Bs[2][BK][BN];   // W tile, k-major

    const int tid   = threadIdx.x;
    const int nBase = blockIdx.x * BN;
    const int mBase = blockIdx.y * BM;

    const int tx = tid & 15;       // neuron micro-tile
    const int ty = tid >> 4;       // batch micro-tile
    const int m0 = ty * 4;
    const int n0 = tx * 4;

    // Per-thread cooperative-load coordinates (2 float4 per matrix per tile)
    int lr[2], lk[2];
#pragma unroll
    for (int l = 0; l < 2; l++) {
        const int f = tid + l * 256;   // 0..511
        lr[l] = f >> 3;                // row within tile (0..63)
        lk[l] = (f & 7) << 2;          // k offset within tile
    }

    // Prologue: load tile 0 into registers, store to smem[0]
    float4 pa[2], pb[2];
#pragma unroll
    for (int l = 0; l < 2; l++) {
        pa[l] = *(const float4*)&x[(mBase + lr[l]) * INPUT_DIM + lk[l]];
        pb[l] = *(const float4*)&W[(nBase + lr[l]) * INPUT_DIM + lk[l]];
    }
#pragma unroll
    for (int l = 0; l < 2; l++) {
        As[0][lk[l] + 0][lr[l]] = pa[l].x;
        As[0][lk[l] + 1][lr[l]] = pa[l].y;
        As[0][lk[l] + 2][lr[l]] = pa[l].z;
        As[0][lk[l] + 3][lr[l]] = pa[l].w;
        Bs[0][lk[l] + 0][lr[l]] = pb[l].x;
        Bs[0][lk[l] + 1][lr[l]] = pb[l].y;
        Bs[0][lk[l] + 2][lr[l]] = pb[l].z;
        Bs[0][lk[l] + 3][lr[l]] = pb[l].w;
    }
    __syncthreads();

    float acc[4][4];
#pragma unroll
    for (int i = 0; i < 4; i++)
#pragma unroll
        for (int j = 0; j < 4; j++) acc[i][j] = 0.0f;

    for (int t = 0; t < KTILES; t++) {
        const int cur = t & 1;
        const int nxt = cur ^ 1;

        // Prefetch next global tile into registers (latency hidden by compute)
        if (t < KTILES - 1) {
            const int k0 = (t + 1) * BK;
#pragma unroll
            for (int l = 0; l < 2; l++) {
                pa[l] = *(const float4*)&x[(mBase + lr[l]) * INPUT_DIM + k0 + lk[l]];
                pb[l] = *(const float4*)&W[(nBase + lr[l]) * INPUT_DIM + k0 + lk[l]];
            }
        }

        // Compute on smem[cur], per-K-tile local accumulators (accuracy),
        // register fragment double buffering.
        float tacc[4][4];
#pragma unroll
        for (int i = 0; i < 4; i++)
#pragma unroll
            for (int j = 0; j < 4; j++) tacc[i][j] = 0.0f;

        float4 af = *(const float4*)&As[cur][0][m0];
        float4 bf = *(const float4*)&Bs[cur][0][n0];
#pragma unroll
        for (int k = 0; k < BK; k++) {
            float4 an, bn;
            if (k < BK - 1) {
                an = *(const float4*)&As[cur][k + 1][m0];
                bn = *(const float4*)&Bs[cur][k + 1][n0];
            }
            const float ar[4] = {af.x, af.y, af.z, af.w};
            const float br[4] = {bf.x, bf.y, bf.z, bf.w};
#pragma unroll
            for (int i = 0; i < 4; i++)
#pragma unroll
                for (int j = 0; j < 4; j++)
                    tacc[i][j] = fmaf(ar[i], br[j], tacc[i][j]);
            af = an; bf = bn;
        }

#pragma unroll
        for (int i = 0; i < 4; i++)
#pragma unroll
            for (int j = 0; j < 4; j++) acc[i][j] += tacc[i][j];

        // Store prefetched tile into the other buffer, then sync
        if (t < KTILES - 1) {
#pragma unroll
            for (int l = 0; l < 2; l++) {
                As[nxt][lk[l] + 0][lr[l]] = pa[l].x;
                As[nxt][lk[l] + 1][lr[l]] = pa[l].y;
                As[nxt][lk[l] + 2][lr[l]] = pa[l].z;
                As[nxt][lk[l] + 3][lr[l]] = pa[l].w;
                Bs[nxt][lk[l] + 0][lr[l]] = pb[l].x;
                Bs[nxt][lk[l] + 1][lr[l]] = pb[l].y;
                Bs[nxt][lk[l] + 2][lr[l]] = pb[l].z;
                Bs[nxt][lk[l] + 3][lr[l]] = pb[l].w;
            }
            __syncthreads();
        }
    }

    // Epilogue: bias + sigmoid, vectorized store
    const float4 bvec = *(const float4*)&bias[nBase + n0];
    const float bb[4] = {bvec.x, bvec.y, bvec.z, bvec.w};
#pragma unroll
    for (int i = 0; i < 4; i++) {
        float4 out;
        float v[4];
#pragma unroll
        for (int j = 0; j < 4; j++) {
            float z = acc[i][j] + bb[j];
            v[j] = 1.0f / (1.0f + expf(-z));
        }
        out.x = v[0]; out.y = v[1]; out.z = v[2]; out.w = v[3];
        *(float4*)&rates[(mBase + m0 + i) * NUM_NEURONS + nBase + n0] = out;
    }
}

// ---------------------------------------------------------------------------
// Kernel B: streaming spike compare.
// grid (TIME_STEPS, BATCH), 256 threads; each block = one (b,t) neuron row
// (2048 elems = 512 float4; 2 float4 per thread).
// __ldcs/__stcs keep the 2MB rates table resident in L2 (evict-first for
// the 210MB u / 210MB spikes streams).
// ---------------------------------------------------------------------------
__global__ __launch_bounds__(256)
void spike_kernel(const float4* __restrict__ u,
                  const float4* __restrict__ rates,
                  float4* __restrict__ spikes) {
    const int b = blockIdx.y;
    const long long base = (long long)b * (TIME_STEPS * NUM_NEURONS / 4)
                         + (long long)blockIdx.x * (NUM_NEURONS / 4);
    const int j = threadIdx.x * 2;                 // local float4 idx (0..510)

    const float4* rrow = rates + b * (NUM_NEURONS / 4);
    const float4 r0 = __ldg(&rrow[j]);
    const float4 r1 = __ldg(&rrow[j + 1]);
    const float4 u0 = __ldcs(&u[base + j]);
    const float4 u1 = __ldcs(&u[base + j + 1]);

    float4 s0, s1;
    s0.x = (u0.x < r0.x) ? 1.0f : 0.0f;
    s0.y = (u0.y < r0.y) ? 1.0f : 0.0f;
    s0.z = (u0.z < r0.z) ? 1.0f : 0.0f;
    s0.w = (u0.w < r0.w) ? 1.0f : 0.0f;
    s1.x = (u1.x < r1.x) ? 1.0f : 0.0f;
    s1.y = (u1.y < r1.y) ? 1.0f : 0.0f;
    s1.z = (u1.z < r1.z) ? 1.0f : 0.0f;
    s1.w = (u1.w < r1.w) ? 1.0f : 0.0f;

    __stcs(&spikes[base + j], s0);
    __stcs(&spikes[base + j + 1], s1);
}

extern "C" void kernel_launch(void* const* d_in, const int* in_sizes, int n_in,
                              void* d_out, int out_size) {
    const float* x = (const float*)d_in[0];
    const float* W = (const float*)d_in[1];
    const float* b = (const float*)d_in[2];
    const float* u = (const float*)d_in[3];

    float* out    = (float*)d_out;
    float* spikes = out;                                               // 52,428,800
    float* rates  = out + (long long)BATCH * TIME_STEPS * NUM_NEURONS; // +524,288

    dim3 gridA(NUM_NEURONS / BN, BATCH / BM);   // (32, 4)
    rates_kernel<<<gridA, 256>>>(x, W, b, rates);

    dim3 gridB(TIME_STEPS, BATCH);              // (100, 256)
    spike_kernel<<<gridB, 256>>>((const float4*)u, (const float4*)rates,
                                 (float4*)spikes);
}

// round 3
// speedup vs baseline: 1.1359x; 1.0756x over previous
#include <cuda_runtime.h>
#include <cuda_bf16.h>
#include <cstdint>

// SpikeEncoder: rates = sigmoid(x @ W^T + b); spikes = (u < rates)
// x: [256,512] f32, W: [2048,512] f32, b: [2048] f32, u: [256,100,2048] f32
// out: spikes [256*100*2048] f32, then rates [256*2048] f32

#define BATCH 256
#define INPUT_DIM 512
#define NUM_NEURONS 2048
#define TIME_STEPS 100

#define TBM 64
#define TBN 64
#define TBK 32
#define NTILES (INPUT_DIM / TBK)   // 16

__device__ __forceinline__ void cp_async16(uint32_t smem_addr, const void* gmem) {
    asm volatile("cp.async.cg.shared.global [%0], [%1], 16;\n"
                 :: "r"(smem_addr), "l"(gmem));
}
__device__ __forceinline__ void cp_commit() {
    asm volatile("cp.async.commit_group;\n" ::: "memory");
}
__device__ __forceinline__ void cp_wait0() {
    asm volatile("cp.async.wait_group 0;\n" ::: "memory");
}

// ---------------------------------------------------------------------------
// Kernel A: tiled fp32 GEMM (C = x @ W^T + b) -> sigmoid -> rates
// 128 threads, 8x4 micro-tile (1.5 B smem / FMA -> pure FFMA-bound).
// Row-major smem tiles with XOR chunk swizzle (conflict-free warp reads),
// cp.async double-buffered, one barrier per k-tile.
// Accumulation: float4 loads along k, dual interleaved accumulators
// (even/odd k pairs) -> accuracy >= previous per-tile tree.
// grid (32, 4).
// ---------------------------------------------------------------------------
__global__ __launch_bounds__(128)
void rates_kernel(const float* __restrict__ x,
                  const float* __restrict__ W,
                  const float* __restrict__ bias,
                  float* __restrict__ rates) {
    // [buf][row*32 + swizzled chunk*4 + e], 64 rows x 32 k floats
    __shared__ float As[2][TBM * TBK];
    __shared__ float Bs[2][TBM * TBK];

    const int tid   = threadIdx.x;
    const int nBase = blockIdx.x * TBN;
    const int mBase = blockIdx.y * TBM;

    // Micro-tile: warp lanes spread across 8 m-groups (A broadcast-friendly)
    // and 4 n-groups (B broadcast-friendly).
    const int m0 = (tid & 7) * 8;    // 8 rows of A per thread
    const int n0 = (tid >> 3) * 4;   // 4 rows of B per thread

    // Cooperative-load coords: 512 float4 per matrix per tile, 4 per thread.
    int lr[4], lc[4];
    uint32_t dstA[4], dstB[4];
    const uint32_t sA = (uint32_t)__cvta_generic_to_shared(&As[0][0]);
    const uint32_t sB = (uint32_t)__cvta_generic_to_shared(&Bs[0][0]);
#pragma unroll
    for (int l = 0; l < 4; l++) {
        const int f = tid + l * 128;        // 0..511
        lr[l] = f >> 3;                     // row 0..63
        lc[l] = f & 7;                      // k-chunk 0..7
        const int sw = lc[l] ^ ((lr[l] >> 2) & 7);
        const uint32_t off = (uint32_t)(lr[l] * TBK + sw * 4) * 4u;
        dstA[l] = sA + off;
        dstB[l] = sB + off;
    }
    const uint32_t bufStride = (uint32_t)(TBM * TBK) * 4u;

    // Prologue: async-load tile 0 into buffer 0
#pragma unroll
    for (int l = 0; l < 4; l++) {
        cp_async16(dstA[l], &x[(mBase + lr[l]) * INPUT_DIM + lc[l] * 4]);
        cp_async16(dstB[l], &W[(nBase + lr[l]) * INPUT_DIM + lc[l] * 4]);
    }
    cp_commit();

    float accL[8][4], accH[8][4];
#pragma unroll
    for (int i = 0; i < 8; i++)
#pragma unroll
        for (int j = 0; j < 4; j++) { accL[i][j] = 0.0f; accH[i][j] = 0.0f; }

    // Precompute per-row smem base offsets + swizzle keys
    int aRow[8], aSwz[8], bRow[4], bSwz[4];
#pragma unroll
    for (int i = 0; i < 8; i++) {
        aRow[i] = (m0 + i) * TBK;
        aSwz[i] = ((m0 + i) >> 2) & 7;
    }
#pragma unroll
    for (int j = 0; j < 4; j++) {
        bRow[j] = (n0 + j) * TBK;
        bSwz[j] = ((n0 + j) >> 2) & 7;
    }

    for (int t = 0; t < NTILES; t++) {
        const int cur = t & 1;
        cp_wait0();            // own async stores from prev iter landed
        __syncthreads();       // everyone's landed + prev compute finished

        if (t < NTILES - 1) {
            const int k0 = (t + 1) * TBK;
            const uint32_t boff = (uint32_t)((t + 1) & 1) * bufStride;
#pragma unroll
            for (int l = 0; l < 4; l++) {
                cp_async16(dstA[l] + boff, &x[(mBase + lr[l]) * INPUT_DIM + k0 + lc[l] * 4]);
                cp_async16(dstB[l] + boff, &W[(nBase + lr[l]) * INPUT_DIM + k0 + lc[l] * 4]);
            }
            cp_commit();
        }

        const float* __restrict__ A = &As[cur][0];
        const float* __restrict__ B = &Bs[cur][0];

#pragma unroll
        for (int s = 0; s < 8; s++) {        // 4 k's per step
            float4 av[8], bv[4];
#pragma unroll
            for (int i = 0; i < 8; i++)
                av[i] = *(const float4*)&A[aRow[i] + ((s ^ aSwz[i]) << 2)];
#pragma unroll
            for (int j = 0; j < 4; j++)
                bv[j] = *(const float4*)&B[bRow[j] + ((s ^ bSwz[j]) << 2)];

#pragma unroll
            for (int i = 0; i < 8; i++)
#pragma unroll
                for (int j = 0; j < 4; j++) {
                    accL[i][j] = fmaf(av[i].x, bv[j].x, accL[i][j]);
                    accH[i][j] = fmaf(av[i].y, bv[j].y, accH[i][j]);
                    accL[i][j] = fmaf(av[i].z, bv[j].z, accL[i][j]);
                    accH[i][j] = fmaf(av[i].w, bv[j].w, accH[i][j]);
                }
        }
    }

    // Epilogue: bias + sigmoid, float4 stores (8 rows x 4 cols per thread)
    const float4 bv4 = *(const float4*)&bias[nBase + n0];
    const float bb[4] = {bv4.x, bv4.y, bv4.z, bv4.w};
#pragma unroll
    for (int i = 0; i < 8; i++) {
        float4 o;
        float v[4];
#pragma unroll
        for (int j = 0; j < 4; j++) {
            const float z = (accL[i][j] + accH[i][j]) + bb[j];
            v[j] = 1.0f / (1.0f + expf(-z));
        }
        o.x = v[0]; o.y = v[1]; o.z = v[2]; o.w = v[3];
        *(float4*)&rates[(mBase + m0 + i) * NUM_NEURONS + nBase + n0] = o;
    }

#if __CUDA_ARCH__ >= 900
    cudaTriggerProgrammaticLaunchCompletion();
#endif
}

// ---------------------------------------------------------------------------
// Kernel B: streaming spike compare. grid (T, BATCH), 256 threads,
// one (b,t) neuron row (8KB) per block. u loads issued BEFORE the PDL
// dependency sync so they overlap the GEMM tail; rates read after.
// __ldcs/__stcs keep the rates table L2-resident.
// ---------------------------------------------------------------------------
__global__ __launch_bounds__(256)
void spike_kernel(const float4* __restrict__ u,
                  const float4* __restrict__ rates,
                  float4* __restrict__ spikes) {
    const int b = blockIdx.y;
    const long long base = (long long)(b * TIME_STEPS + blockIdx.x) * (NUM_NEURONS / 4);
    const int j = threadIdx.x * 2;

    const float4 u0 = __ldcs(&u[base + j]);
    const float4 u1 = __ldcs(&u[base + j + 1]);

#if __CUDA_ARCH__ >= 900
    cudaGridDependencySynchronize();
#endif

    const float4* rrow = rates + b * (NUM_NEURONS / 4);
    const float4 r0 = __ldg(&rrow[j]);
    const float4 r1 = __ldg(&rrow[j + 1]);

    float4 s0, s1;
    s0.x = (u0.x < r0.x) ? 1.0f : 0.0f;
    s0.y = (u0.y < r0.y) ? 1.0f : 0.0f;
    s0.z = (u0.z < r0.z) ? 1.0f : 0.0f;
    s0.w = (u0.w < r0.w) ? 1.0f : 0.0f;
    s1.x = (u1.x < r1.x) ? 1.0f : 0.0f;
    s1.y = (u1.y < r1.y) ? 1.0f : 0.0f;
    s1.z = (u1.z < r1.z) ? 1.0f : 0.0f;
    s1.w = (u1.w < r1.w) ? 1.0f : 0.0f;

    __stcs(&spikes[base + j], s0);
    __stcs(&spikes[base + j + 1], s1);
}

extern "C" void kernel_launch(void* const* d_in, const int* in_sizes, int n_in,
                              void* d_out, int out_size) {
    const float* x = (const float*)d_in[0];
    const float* W = (const float*)d_in[1];
    const float* b = (const float*)d_in[2];
    const float* u = (const float*)d_in[3];

    float* out    = (float*)d_out;
    float* spikes = out;                                               // 52,428,800
    float* rates  = out + (long long)BATCH * TIME_STEPS * NUM_NEURONS; // +524,288

    dim3 gridA(NUM_NEURONS / TBN, BATCH / TBM);   // (32, 4)
    rates_kernel<<<gridA, 128>>>(x, W, b, rates);

    // Spike kernel with PDL (programmatic stream serialization) so its u
    // loads overlap the GEMM tail. Fallback to a plain launch on error.
    const float4* u4 = (const float4*)u;
    const float4* r4 = (const float4*)rates;
    float4*       s4 = (float4*)spikes;

    cudaLaunchConfig_t cfg = {};
    cfg.gridDim  = dim3(TIME_STEPS, BATCH, 1);    // (100, 256)
    cfg.blockDim = dim3(256, 1, 1);
    cfg.dynamicSmemBytes = 0;
    cfg.stream = 0;
    cudaLaunchAttribute attrs[1];
    attrs[0].id = cudaLaunchAttributeProgrammaticStreamSerialization;
    attrs[0].val.programmaticStreamSerializationAllowed = 1;
    cfg.attrs = attrs;
    cfg.numAttrs = 1;

    cudaError_t e = cudaLaunchKernelEx(&cfg, spike_kernel, u4, r4, s4);
    if (e != cudaSuccess) {
        (void)cudaGetLastError();  // clear
        spike_kernel<<<dim3(TIME_STEPS, BATCH, 1), 256>>>(u4, r4, s4);
    }
}